// round 1
// baseline (speedup 1.0000x reference)
#include <cuda_runtime.h>
#include <cuda_bf16.h>

// Problem constants
#define NN 110          // nodes
#define CC 4096         // channels
#define NPAD 128        // padded node dim (for small-K GEMMs)

// GEMM tile config
#define BM 128
#define BN 32
#define BK 32
#define BMP 132         // padded shared A row (bank-conflict mitigation, float4-aligned)
#define BNP 36
#define NTHREADS 128

// Scratch (device globals: zero-initialized at module load; rows >= 110 are
// never written, so B-side reads of padded rows always see zeros).
__device__ float g_h   [NPAD * CC];
__device__ float g_aggr[NPAD * CC];
__device__ float g_out1[NPAD * CC];
__device__ float g_Mn  [NPAD * NPAD];   // normalized transposed mask, lda=128
__device__ float g_Wlp [NPAD * NPAD];   // Wl padded to lda=128

// ---------------------------------------------------------------------------
// Prep: build Mn[j][i] = (adj[i][j] != 0) / max(deg_j, 1), and pad Wl.
// ---------------------------------------------------------------------------
__global__ void prep_kernel(const int* __restrict__ adj, const float* __restrict__ Wl) {
    int j = threadIdx.x;
    if (j >= NPAD) return;
    float inv = 0.0f;
    if (j < NN) {
        int deg = 0;
        for (int i = 0; i < NN; ++i) deg += (adj[i * NN + j] != 0);
        inv = 1.0f / (float)(deg > 1 ? deg : 1);
    }
    for (int i = 0; i < NPAD; ++i) {
        float mv = 0.0f, wv = 0.0f;
        if (j < NN && i < NN) {
            if (adj[i * NN + j] != 0) mv = inv;
            wv = Wl[j * NN + i];
        }
        g_Mn [j * NPAD + i] = mv;
        g_Wlp[j * NPAD + i] = wv;
    }
}

// ---------------------------------------------------------------------------
// Generic fp32 GEMM: C[M x N] = A1[M x K1] @ B1[K1 x N] (+ A2 @ B2) (+ bias)
// A row-major with stride lda (multiple of 4); B row-major stride N.
// K1, K2 multiples of BK. bias_mode: 0=none, 1=per-col, 2=per-row.
// Tile: BM=128 x BN=32, BK=32, 128 threads, thread computes 2x(4x4) raked outputs.
// Register-staged double buffering of global loads.
// ---------------------------------------------------------------------------
__global__ __launch_bounds__(NTHREADS)
void sgemm_kernel(const float* __restrict__ A1, int lda1, int K1,
                  const float* __restrict__ B1,
                  const float* __restrict__ A2, int lda2, int K2,
                  const float* __restrict__ B2,
                  const float* __restrict__ bias, int bias_mode, int do_relu,
                  float* __restrict__ C, int M, int N)
{
    __shared__ __align__(16) float As[BK][BMP];
    __shared__ __align__(16) float Bs[BK][BNP];

    const int tid  = threadIdx.x;
    const int mgrp = tid & 15;          // 0..15 -> output rows mgrp*4..+3 and 64+mgrp*4..+3
    const int ngrp = tid >> 4;          // 0..7  -> output cols ngrp*4..+3
    const int bn   = blockIdx.x * BN;

    // loader decomposition (shared by A and B loaders)
    const int lrow = tid >> 3;          // 0..15 (advance +16 per pass)
    const int lcol = (tid & 7) * 4;     // float4 offset

    const int tiles1 = K1 / BK;
    const int tiles2 = (A2 != nullptr) ? (K2 / BK) : 0;
    const int ntiles = tiles1 + tiles2;

    float acc[2][4][4];
#pragma unroll
    for (int p = 0; p < 2; ++p)
#pragma unroll
        for (int i = 0; i < 4; ++i)
#pragma unroll
            for (int j = 0; j < 4; ++j) acc[p][i][j] = 0.0f;

    float4 ar[8];
    float4 br[2];
    const float4 f4z = make_float4(0.f, 0.f, 0.f, 0.f);

#define LOAD_TILE(T)                                                            \
    do {                                                                        \
        const float* Ap; const float* Bp; int lda_; int k0_;                    \
        if ((T) < tiles1) { Ap = A1; Bp = B1; lda_ = lda1; k0_ = (T) * BK; }    \
        else { Ap = A2; Bp = B2; lda_ = lda2; k0_ = ((T) - tiles1) * BK; }      \
        _Pragma("unroll")                                                       \
        for (int p = 0; p < 8; ++p) {                                           \
            int m = p * 16 + lrow;                                              \
            ar[p] = (m < M) ? *(const float4*)(Ap + (size_t)m * lda_ + k0_ + lcol) : f4z; \
        }                                                                       \
        _Pragma("unroll")                                                       \
        for (int p = 0; p < 2; ++p) {                                           \
            int kk = p * 16 + lrow;                                             \
            br[p] = *(const float4*)(Bp + (size_t)(k0_ + kk) * N + bn + lcol);  \
        }                                                                       \
    } while (0)

    LOAD_TILE(0);

    for (int t = 0; t < ntiles; ++t) {
        __syncthreads();   // previous tile's compute finished (no-op at t=0)

        // stage regs -> shared (A transposed to k-major)
#pragma unroll
        for (int p = 0; p < 8; ++p) {
            int m = p * 16 + lrow;
            As[lcol + 0][m] = ar[p].x;
            As[lcol + 1][m] = ar[p].y;
            As[lcol + 2][m] = ar[p].z;
            As[lcol + 3][m] = ar[p].w;
        }
#pragma unroll
        for (int p = 0; p < 2; ++p) {
            int kk = p * 16 + lrow;
            *(float4*)&Bs[kk][lcol] = br[p];
        }
        __syncthreads();

        if (t + 1 < ntiles) LOAD_TILE(t + 1);   // LDG latency hides under compute

#pragma unroll
        for (int k = 0; k < BK; ++k) {
            float4 a0 = *(const float4*)&As[k][mgrp * 4];
            float4 a1 = *(const float4*)&As[k][64 + mgrp * 4];
            float4 b  = *(const float4*)&Bs[k][ngrp * 4];
            float av0[4] = {a0.x, a0.y, a0.z, a0.w};
            float av1[4] = {a1.x, a1.y, a1.z, a1.w};
            float bv[4]  = {b.x, b.y, b.z, b.w};
#pragma unroll
            for (int i = 0; i < 4; ++i)
#pragma unroll
                for (int j = 0; j < 4; ++j) {
                    acc[0][i][j] = fmaf(av0[i], bv[j], acc[0][i][j]);
                    acc[1][i][j] = fmaf(av1[i], bv[j], acc[1][i][j]);
                }
        }
    }
#undef LOAD_TILE

    // epilogue
    float bcol[4] = {0.f, 0.f, 0.f, 0.f};
    if (bias_mode == 1) {
#pragma unroll
        for (int j = 0; j < 4; ++j) bcol[j] = bias[bn + ngrp * 4 + j];
    }
#pragma unroll
    for (int p = 0; p < 2; ++p) {
#pragma unroll
        for (int i = 0; i < 4; ++i) {
            int r = p * 64 + mgrp * 4 + i;
            if (r < M) {
                float brow = (bias_mode == 2) ? bias[r] : 0.0f;
                float4 v;
                v.x = acc[p][i][0] + bcol[0] + brow;
                v.y = acc[p][i][1] + bcol[1] + brow;
                v.z = acc[p][i][2] + bcol[2] + brow;
                v.w = acc[p][i][3] + bcol[3] + brow;
                if (do_relu) {
                    v.x = fmaxf(v.x, 0.f); v.y = fmaxf(v.y, 0.f);
                    v.z = fmaxf(v.z, 0.f); v.w = fmaxf(v.w, 0.f);
                }
                *(float4*)&C[(size_t)r * N + bn + ngrp * 4] = v;
            }
        }
    }
}

// ---------------------------------------------------------------------------
// Launch
// ---------------------------------------------------------------------------
extern "C" void kernel_launch(void* const* d_in, const int* in_sizes, int n_in,
                              void* d_out, int out_size)
{
    const float* x   = (const float*)d_in[0];   // [110, 4096]
    const int*   adj = (const int*)  d_in[1];   // [110, 110]
    const float* W2  = (const float*)d_in[2];   // [4096, 4096] (in, out)
    const float* b2  = (const float*)d_in[3];   // [4096]
    const float* W1  = (const float*)d_in[4];   // [8192, 4096] (in, out)
    const float* b1  = (const float*)d_in[5];   // [4096]
    const float* Wl  = (const float*)d_in[6];   // [110, 110]
    const float* bl  = (const float*)d_in[7];   // [110]
    float* out = (float*)d_out;                 // [110, 4096]

    float *h, *aggr, *out1, *Mn, *Wlp;
    cudaGetSymbolAddress((void**)&h,    g_h);
    cudaGetSymbolAddress((void**)&aggr, g_aggr);
    cudaGetSymbolAddress((void**)&out1, g_out1);
    cudaGetSymbolAddress((void**)&Mn,   g_Mn);
    cudaGetSymbolAddress((void**)&Wlp,  g_Wlp);

    dim3 grid(CC / BN);     // 128 blocks
    dim3 block(NTHREADS);

    // 0) normalized adjacency + padded Wl
    prep_kernel<<<1, NPAD>>>(adj, Wl);

    // 1) h = x @ W2 + b2
    sgemm_kernel<<<grid, block>>>(x, CC, CC, W2,
                                  nullptr, 0, 0, nullptr,
                                  b2, /*bias_mode=*/1, /*relu=*/0,
                                  h, NN, CC);

    // 2) aggr = Mn @ h    (K padded to 128; pad rows/cols are zero)
    sgemm_kernel<<<grid, block>>>(Mn, NPAD, NPAD, h,
                                  nullptr, 0, 0, nullptr,
                                  nullptr, 0, 0,
                                  aggr, NN, CC);

    // 3) out1 = relu(h @ W1[0:4096] + aggr @ W1[4096:8192] + b1)
    sgemm_kernel<<<grid, block>>>(h,    CC, CC, W1,
                                  aggr, CC, CC, W1 + (size_t)CC * CC,
                                  b1, /*bias_mode=*/1, /*relu=*/1,
                                  out1, NN, CC);

    // 4) out = Wl @ out1 + bl[:, None]
    sgemm_kernel<<<grid, block>>>(Wlp, NPAD, NPAD, out1,
                                  nullptr, 0, 0, nullptr,
                                  bl, /*bias_mode=*/2, /*relu=*/0,
                                  out, NN, CC);
}

// round 3
// speedup vs baseline: 1.8845x; 1.8845x over previous
#include <cuda_runtime.h>
#include <cuda_bf16.h>
#include <cstdint>

#define NN 110
#define CC 4096
#define NPAD 128

#define BM 128
#define BN 32
#define BKC 64          // fp32 k per chunk
#define PITCH 72        // bf16 elems per smem row (64 + 8 pad -> conflict-free ldmatrix)
#define NTH 256

// -------------------- scratch (zero-initialized device globals) ------------
__device__ float g_h   [NPAD * CC];
__device__ float g_aggr[NPAD * CC];
__device__ float g_out1[NPAD * CC];
__device__ float g_Mn  [NPAD * NPAD];
__device__ float g_Wlp [NPAD * NPAD];

// -------------------- helpers ----------------------------------------------
__device__ __forceinline__ uint32_t smem_u32(const void* p) {
    uint32_t a;
    asm("{ .reg .u64 t; cvta.to.shared.u64 t, %1; cvt.u32.u64 %0, t; }"
        : "=r"(a) : "l"(p));
    return a;
}

// split fp32 pair -> bf16x2 hi word and lo word (lo = rn(x - hi))
__device__ __forceinline__ void split2(float x0, float x1, uint32_t& hi, uint32_t& lo) {
    uint32_t h;
    asm("cvt.rn.bf16x2.f32 %0, %1, %2;" : "=r"(h) : "f"(x1), "f"(x0));
    float h0 = __uint_as_float(h << 16);
    float h1 = __uint_as_float(h & 0xFFFF0000u);
    float r0 = x0 - h0;
    float r1 = x1 - h1;
    asm("cvt.rn.bf16x2.f32 %0, %1, %2;" : "=r"(lo) : "f"(r1), "f"(r0));
    hi = h;
}

#define LDMX4(r, addr)                                                        \
    asm volatile("ldmatrix.sync.aligned.m8n8.x4.shared.b16 {%0,%1,%2,%3}, [%4];" \
        : "=r"((r)[0]), "=r"((r)[1]), "=r"((r)[2]), "=r"((r)[3]) : "r"(addr))

#define MMA_BF16(acc, a, b0, b1)                                              \
    asm volatile("mma.sync.aligned.m16n8k16.row.col.f32.bf16.bf16.f32 "       \
        "{%0,%1,%2,%3}, {%4,%5,%6,%7}, {%8,%9}, {%0,%1,%2,%3};"               \
        : "+f"((acc)[0]), "+f"((acc)[1]), "+f"((acc)[2]), "+f"((acc)[3])      \
        : "r"((a)[0]), "r"((a)[1]), "r"((a)[2]), "r"((a)[3]), "r"(b0), "r"(b1))

// ---------------------------------------------------------------------------
// Prep: Mn[j][i] = (adj[i][j] != 0)/max(deg_j,1); pad Wl to lda=128.
// ---------------------------------------------------------------------------
__global__ void prep_kernel(const int* __restrict__ adj, const float* __restrict__ Wl) {
    int j = threadIdx.x;
    if (j >= NPAD) return;
    float inv = 0.0f;
    if (j < NN) {
        int deg = 0;
        for (int i = 0; i < NN; ++i) deg += (adj[i * NN + j] != 0);
        inv = 1.0f / (float)(deg > 1 ? deg : 1);
    }
    for (int i = 0; i < NPAD; ++i) {
        float mv = 0.0f, wv = 0.0f;
        if (j < NN && i < NN) {
            if (adj[i * NN + j] != 0) mv = inv;
            wv = Wl[j * NN + i];
        }
        g_Mn [j * NPAD + i] = mv;
        g_Wlp[j * NPAD + i] = wv;
    }
}

// ---------------------------------------------------------------------------
// bf16-split HMMA GEMM (mma.sync m16n8k16):
//   C[0:Mreal, n0:n0+32] = A1[Mreal x ka1] @ B1[ka1 x N] (+ A2 @ B2) (+ bias)
// A row-major stride lda; B row-major stride ldb. ka multiples of 64.
// bias_mode: 0 none, 1 per-col, 2 per-row.
// ---------------------------------------------------------------------------
__global__ __launch_bounds__(NTH)
void tgemm(const float* __restrict__ A1, int lda1, int ka1,
           const float* __restrict__ B1, int ldb1,
           const float* __restrict__ A2, int lda2, int ka2,
           const float* __restrict__ B2, int ldb2,
           const float* __restrict__ bias, int bias_mode, int do_relu,
           float* __restrict__ C, int ldc, int Mreal)
{
    __shared__ __align__(16) __nv_bfloat16 AsH[BM * PITCH];
    __shared__ __align__(16) __nv_bfloat16 AsL[BM * PITCH];
    __shared__ __align__(16) __nv_bfloat16 BsH[BN * PITCH];
    __shared__ __align__(16) __nv_bfloat16 BsL[BN * PITCH];

    const int tid = threadIdx.x;
    const int wid = tid >> 5;
    const int lid = tid & 31;
    const int warpm = wid >> 1;      // 0..3  -> m base warpm*32
    const int warpn = wid & 1;       // 0..1  -> n base warpn*16
    const int n0 = blockIdx.x * BN;

    // A loader: 128 rows x 64 k fp32, float4, 8 passes
    const int alrow = tid >> 4;          // 0..15
    const int alc   = (tid & 15) * 4;    // k offset in floats
    // B loader: 64 k x 32 n, coalesced along n
    const int bkb = (tid >> 5) * 8;      // 8 k per thread
    const int bnn = tid & 31;            // n index

    const int T1 = ka1 / BKC;
    const int T2 = (A2 != nullptr) ? (ka2 / BKC) : 0;
    const int T  = T1 + T2;

    float acc[2][2][4];
#pragma unroll
    for (int a = 0; a < 2; ++a)
#pragma unroll
        for (int b = 0; b < 2; ++b)
#pragma unroll
            for (int c = 0; c < 4; ++c) acc[a][b][c] = 0.0f;

    // ldmatrix base addresses (per thread, fixed for the whole kernel)
    const uint32_t aRowSel = (uint32_t)(lid & 15);
    const uint32_t aColSel = (uint32_t)((lid >> 4) & 1) * 8u;
    uint32_t aBaseH = smem_u32(AsH) + ((warpm * 32 + aRowSel) * PITCH + aColSel) * 2u;
    uint32_t aBaseL = smem_u32(AsL) + ((warpm * 32 + aRowSel) * PITCH + aColSel) * 2u;
    const uint32_t bRowSel = (uint32_t)((lid & 7) + ((lid >> 4) & 1) * 8);
    const uint32_t bColSel = (uint32_t)(lid & 8);
    uint32_t bBaseH = smem_u32(BsH) + ((warpn * 16 + bRowSel) * PITCH + bColSel) * 2u;
    uint32_t bBaseL = smem_u32(BsL) + ((warpn * 16 + bRowSel) * PITCH + bColSel) * 2u;

    float4 fa[8];
    float  fb[8];
    const float4 f4z = make_float4(0.f, 0.f, 0.f, 0.f);

#define LOADG(T_)                                                              \
    do {                                                                       \
        const float* A; const float* B; int lda_, ldb_, k0_;                   \
        if ((T_) < T1) { A = A1; B = B1; lda_ = lda1; ldb_ = ldb1; k0_ = (T_) * BKC; } \
        else { A = A2; B = B2; lda_ = lda2; ldb_ = ldb2; k0_ = ((T_) - T1) * BKC; }    \
        _Pragma("unroll")                                                      \
        for (int p = 0; p < 8; ++p) {                                          \
            int m = p * 16 + alrow;                                            \
            fa[p] = (m < Mreal) ? *(const float4*)(A + (size_t)m * lda_ + k0_ + alc) : f4z; \
        }                                                                      \
        _Pragma("unroll")                                                      \
        for (int i = 0; i < 8; ++i)                                            \
            fb[i] = B[(size_t)(k0_ + bkb + i) * ldb_ + n0 + bnn];              \
    } while (0)

    LOADG(0);

    for (int t = 0; t < T; ++t) {
        __syncthreads();   // previous compute done (no-op at t=0)

        // convert + store stage
#pragma unroll
        for (int p = 0; p < 8; ++p) {
            int row = p * 16 + alrow;
            uint32_t h0, l0, h1, l1;
            split2(fa[p].x, fa[p].y, h0, l0);
            split2(fa[p].z, fa[p].w, h1, l1);
            uint32_t off = (uint32_t)row * PITCH + (uint32_t)alc;  // bf16 elems
            *(uint2*)((char*)AsH + off * 2) = make_uint2(h0, h1);
            *(uint2*)((char*)AsL + off * 2) = make_uint2(l0, l1);
        }
#pragma unroll
        for (int i = 0; i < 8; ++i) {
            float x = fb[i];
            __nv_bfloat16 h = __float2bfloat16(x);
            __nv_bfloat16 l = __float2bfloat16(x - __bfloat162float(h));
            uint32_t off = (uint32_t)bnn * PITCH + (uint32_t)(bkb + i);
            BsH[off] = h;
            BsL[off] = l;
        }
        __syncthreads();

        if (t + 1 < T) LOADG(t + 1);   // LDG overlaps compute

        // compute: 4 k-steps of 16
#pragma unroll
        for (int ks = 0; ks < 4; ++ks) {
            uint32_t ah[2][4], al[2][4], bh[4], bl[4];
            const uint32_t ko = (uint32_t)ks * 32u;     // 16 bf16 = 32 bytes
            LDMX4(ah[0], aBaseH + ko);
            LDMX4(ah[1], aBaseH + 16u * PITCH * 2u + ko);
            LDMX4(al[0], aBaseL + ko);
            LDMX4(al[1], aBaseL + 16u * PITCH * 2u + ko);
            LDMX4(bh, bBaseH + ko);
            LDMX4(bl, bBaseL + ko);
#pragma unroll
            for (int mt = 0; mt < 2; ++mt)
#pragma unroll
                for (int nt = 0; nt < 2; ++nt) {
                    MMA_BF16(acc[mt][nt], ah[mt], bh[2 * nt], bh[2 * nt + 1]);
                    MMA_BF16(acc[mt][nt], ah[mt], bl[2 * nt], bl[2 * nt + 1]);
                    MMA_BF16(acc[mt][nt], al[mt], bh[2 * nt], bh[2 * nt + 1]);
                }
        }
    }
#undef LOADG

    // epilogue: fragment c: lane -> rows g, g+8; cols 2t, 2t+1
    const int g  = lid >> 2;
    const int tq = lid & 3;
#pragma unroll
    for (int mt = 0; mt < 2; ++mt) {
#pragma unroll
        for (int nt = 0; nt < 2; ++nt) {
            int col = n0 + warpn * 16 + nt * 8 + tq * 2;
            float bc0 = 0.f, bc1 = 0.f;
            if (bias_mode == 1) { bc0 = bias[col]; bc1 = bias[col + 1]; }
            int m0 = warpm * 32 + mt * 16 + g;
            int m1 = m0 + 8;
            if (m0 < Mreal) {
                float rb = (bias_mode == 2) ? bias[m0] : 0.0f;
                float2 v = make_float2(acc[mt][nt][0] + bc0 + rb,
                                       acc[mt][nt][1] + bc1 + rb);
                if (do_relu) { v.x = fmaxf(v.x, 0.f); v.y = fmaxf(v.y, 0.f); }
                *(float2*)&C[(size_t)m0 * ldc + col] = v;
            }
            if (m1 < Mreal) {
                float rb = (bias_mode == 2) ? bias[m1] : 0.0f;
                float2 v = make_float2(acc[mt][nt][2] + bc0 + rb,
                                       acc[mt][nt][3] + bc1 + rb);
                if (do_relu) { v.x = fmaxf(v.x, 0.f); v.y = fmaxf(v.y, 0.f); }
                *(float2*)&C[(size_t)m1 * ldc + col] = v;
            }
        }
    }
}

// ---------------------------------------------------------------------------
extern "C" void kernel_launch(void* const* d_in, const int* in_sizes, int n_in,
                              void* d_out, int out_size)
{
    const float* x   = (const float*)d_in[0];
    const int*   adj = (const int*)  d_in[1];
    const float* W2  = (const float*)d_in[2];
    const float* b2  = (const float*)d_in[3];
    const float* W1  = (const float*)d_in[4];
    const float* b1  = (const float*)d_in[5];
    const float* Wl  = (const float*)d_in[6];
    const float* bl  = (const float*)d_in[7];
    float* out = (float*)d_out;

    float *h, *aggr, *out1, *Mn, *Wlp;
    cudaGetSymbolAddress((void**)&h,    g_h);
    cudaGetSymbolAddress((void**)&aggr, g_aggr);
    cudaGetSymbolAddress((void**)&out1, g_out1);
    cudaGetSymbolAddress((void**)&Mn,   g_Mn);
    cudaGetSymbolAddress((void**)&Wlp,  g_Wlp);

    dim3 g(CC / BN), b(NTH);   // 128 CTAs

    prep_kernel<<<1, NPAD>>>(adj, Wl);

    // K1: h = x @ W2 + b2
    tgemm<<<g, b>>>(x, CC, CC, W2, CC,
                    nullptr, 0, 0, nullptr, 0,
                    b2, 1, 0, h, CC, NN);
    // K2: aggr = Mn @ h
    tgemm<<<g, b>>>(Mn, NPAD, NPAD, h, CC,
                    nullptr, 0, 0, nullptr, 0,
                    nullptr, 0, 0, aggr, CC, NN);
    // K3: out1 = relu(h @ W1_top + aggr @ W1_bot + b1)
    tgemm<<<g, b>>>(h, CC, CC, W1, CC,
                    aggr, CC, CC, W1 + (size_t)CC * CC, CC,
                    b1, 1, 1, out1, CC, NN);
    // K4: out = Wlp @ out1 + bl[:, None]
    tgemm<<<g, b>>>(Wlp, NPAD, NPAD, out1, CC,
                    nullptr, 0, 0, nullptr, 0,
                    bl, 2, 0, out, CC, NN);
}